// round 1
// baseline (speedup 1.0000x reference)
#include <cuda_runtime.h>
#include <cstdint>

// Problem constants (fixed by the dataset)
#define N_SRC   50000
#define N_EDGES 150000
#define D       512     // D_IN == D_OUT == 512

// Scratch: aggregated messages, zeroed each launch. 50000*512*4B = 102.4 MB.
__device__ float g_agg[(size_t)N_SRC * D];

// ---------------------------------------------------------------------------
// Kernel 1: zero the aggregation buffer (grid-stride float4 stores)
// ---------------------------------------------------------------------------
__global__ void zero_agg_kernel() {
    size_t total4 = (size_t)N_SRC * D / 4;
    size_t i = (size_t)blockIdx.x * blockDim.x + threadIdx.x;
    size_t stride = (size_t)gridDim.x * blockDim.x;
    float4 z = make_float4(0.f, 0.f, 0.f, 0.f);
    float4* p = reinterpret_cast<float4*>(g_agg);
    for (; i < total4; i += stride) p[i] = z;
}

// ---------------------------------------------------------------------------
// Kernel 2: edge scatter-add.  One block (128 threads) per edge.
// Each thread moves one float4 (128 * 4 = 512 floats = one row).
// Uses vectorized red.global.add.v4.f32 (sm_90+) — 4x fewer L2 atomic ops.
// ---------------------------------------------------------------------------
__global__ void __launch_bounds__(128) scatter_kernel(
    const float* __restrict__ src_h,
    const int*   __restrict__ src_idx,
    const int*   __restrict__ dst_idx)
{
    int e = blockIdx.x;
    int s = src_idx[e];
    int d = dst_idx[e];
    int t = threadIdx.x;  // 0..127

    const float4* srow = reinterpret_cast<const float4*>(src_h + (size_t)s * D);
    float4 v = srow[t];

    float* dptr = g_agg + (size_t)d * D + (size_t)t * 4;
    asm volatile("red.global.add.v4.f32 [%0], {%1, %2, %3, %4};"
                 :: "l"(dptr), "f"(v.x), "f"(v.y), "f"(v.z), "f"(v.w)
                 : "memory");
}

// ---------------------------------------------------------------------------
// Kernel 3: out = agg @ W^T + b  via TF32 tensor cores (mma.sync.m16n8k8).
//   out[i][j] = sum_k agg[i][k] * W[j][k]      (both K-major, "NT" gemm)
// Tiles: BM=128, BN=128, BK=32; 256 threads (8 warps, 2x4), warp tile 64x32.
// ---------------------------------------------------------------------------
#define BM 128
#define BN 128
#define BK 32

__device__ __forceinline__ unsigned f32_to_tf32(float f) {
    unsigned r;
    asm("cvt.rna.tf32.f32 %0, %1;" : "=r"(r) : "f"(f));
    return r;
}

__device__ __forceinline__ void mma_tf32_16x8x8(
    float d[4], const unsigned a[4], const unsigned b[2], const float c[4])
{
    asm volatile(
        "mma.sync.aligned.m16n8k8.row.col.f32.tf32.tf32.f32 "
        "{%0,%1,%2,%3}, {%4,%5,%6,%7}, {%8,%9}, {%10,%11,%12,%13};"
        : "=f"(d[0]), "=f"(d[1]), "=f"(d[2]), "=f"(d[3])
        : "r"(a[0]), "r"(a[1]), "r"(a[2]), "r"(a[3]),
          "r"(b[0]), "r"(b[1]),
          "f"(c[0]), "f"(c[1]), "f"(c[2]), "f"(c[3]));
}

__global__ void __launch_bounds__(256) gemm_kernel(
    const float* __restrict__ W,
    const float* __restrict__ bias,
    float*       __restrict__ out)
{
    __shared__ unsigned As[BM][BK + 1];
    __shared__ unsigned Bs[BN][BK + 1];

    const int tid  = threadIdx.x;
    const int warp = tid >> 5;
    const int lane = tid & 31;
    const int g    = lane >> 2;   // group id 0..7
    const int t    = lane & 3;    // thread-in-group 0..3

    const int wm = (warp & 1) * 64;   // warp M offset within block (2 warps)
    const int wn = (warp >> 1) * 32;  // warp N offset within block (4 warps)

    const int bm = blockIdx.y * BM;
    const int bn = blockIdx.x * BN;

    float acc[4][4][4];
    #pragma unroll
    for (int mt = 0; mt < 4; mt++)
        #pragma unroll
        for (int nt = 0; nt < 4; nt++)
            #pragma unroll
            for (int r = 0; r < 4; r++)
                acc[mt][nt][r] = 0.f;

    // Cooperative tile-load indexing: 256 threads, each pass covers 32 rows
    // of 8 float4 columns (BK=32 floats per row).
    const int lr = tid >> 3;          // 0..31
    const int lc = (tid & 7) * 4;     // 0,4,...,28

    for (int k0 = 0; k0 < D; k0 += BK) {
        #pragma unroll
        for (int i = 0; i < 4; i++) {
            int row  = lr + i * 32;          // 0..127
            // A tile (agg), M-bounds guarded
            int arow = bm + row;
            float4 va = make_float4(0.f, 0.f, 0.f, 0.f);
            if (arow < N_SRC)
                va = *reinterpret_cast<const float4*>(
                        g_agg + (size_t)arow * D + k0 + lc);
            As[row][lc + 0] = f32_to_tf32(va.x);
            As[row][lc + 1] = f32_to_tf32(va.y);
            As[row][lc + 2] = f32_to_tf32(va.z);
            As[row][lc + 3] = f32_to_tf32(va.w);
            // B tile (W rows), always in-bounds (N = K = 512)
            int brow = bn + row;
            float4 vb = *reinterpret_cast<const float4*>(
                        W + (size_t)brow * D + k0 + lc);
            Bs[row][lc + 0] = f32_to_tf32(vb.x);
            Bs[row][lc + 1] = f32_to_tf32(vb.y);
            Bs[row][lc + 2] = f32_to_tf32(vb.z);
            Bs[row][lc + 3] = f32_to_tf32(vb.w);
        }
        __syncthreads();

        #pragma unroll
        for (int kk = 0; kk < BK; kk += 8) {
            unsigned afr[4][4];
            unsigned bfr[4][2];
            #pragma unroll
            for (int mt = 0; mt < 4; mt++) {
                int r = wm + mt * 16 + g;
                afr[mt][0] = As[r    ][kk + t    ];
                afr[mt][1] = As[r + 8][kk + t    ];
                afr[mt][2] = As[r    ][kk + t + 4];
                afr[mt][3] = As[r + 8][kk + t + 4];
            }
            #pragma unroll
            for (int nt = 0; nt < 4; nt++) {
                int c = wn + nt * 8 + g;
                bfr[nt][0] = Bs[c][kk + t    ];
                bfr[nt][1] = Bs[c][kk + t + 4];
            }
            #pragma unroll
            for (int mt = 0; mt < 4; mt++)
                #pragma unroll
                for (int nt = 0; nt < 4; nt++)
                    mma_tf32_16x8x8(acc[mt][nt], afr[mt], bfr[nt], acc[mt][nt]);
        }
        __syncthreads();
    }

    // Epilogue: add bias, store
    #pragma unroll
    for (int mt = 0; mt < 4; mt++) {
        #pragma unroll
        for (int nt = 0; nt < 4; nt++) {
            int row0 = bm + wm + mt * 16 + g;
            int row1 = row0 + 8;
            int col  = bn + wn + nt * 8 + 2 * t;
            float b0 = __ldg(bias + col);
            float b1 = __ldg(bias + col + 1);
            if (row0 < N_SRC) {
                out[(size_t)row0 * D + col    ] = acc[mt][nt][0] + b0;
                out[(size_t)row0 * D + col + 1] = acc[mt][nt][1] + b1;
            }
            if (row1 < N_SRC) {
                out[(size_t)row1 * D + col    ] = acc[mt][nt][2] + b0;
                out[(size_t)row1 * D + col + 1] = acc[mt][nt][3] + b1;
            }
        }
    }
}

// ---------------------------------------------------------------------------
// Launch. Inputs per metadata order:
//   0: src_h [50000,512] f32   1: W [512,512] f32   2: b [512] f32
//   3: src_idx [150000] i32    4: dst_idx [150000] i32   5: n_dst scalar
// ---------------------------------------------------------------------------
extern "C" void kernel_launch(void* const* d_in, const int* in_sizes, int n_in,
                              void* d_out, int out_size)
{
    const float* src_h   = (const float*)d_in[0];
    const float* W       = (const float*)d_in[1];
    const float* bias    = (const float*)d_in[2];
    const int*   src_idx = (const int*)d_in[3];
    const int*   dst_idx = (const int*)d_in[4];
    float*       out     = (float*)d_out;

    zero_agg_kernel<<<1184, 256>>>();                     // 102.4 MB -> 0
    scatter_kernel<<<N_EDGES, 128>>>(src_h, src_idx, dst_idx);
    dim3 grid(D / BN, (N_SRC + BM - 1) / BM);             // (4, 391)
    gemm_kernel<<<grid, 256>>>(W, bias, out);
}

// round 2
// speedup vs baseline: 1.7728x; 1.7728x over previous
#include <cuda_runtime.h>
#include <cstdint>

// Problem constants (fixed by the dataset)
#define N_SRC   50000
#define N_EDGES 150000
#define D       512
#define NBLK_N  196          // ceil(N_SRC / 256)
#define NBLK_E  587          // ceil(N_EDGES / 256)

// ---------------------------------------------------------------------------
// Device scratch (no allocations allowed)
// ---------------------------------------------------------------------------
__device__ float g_agg[(size_t)N_SRC * D];     // aggregated messages, 102.4 MB
__device__ int   g_count[N_SRC];
__device__ int   g_offset[N_SRC + 1];          // CSR row offsets
__device__ int   g_cursor[N_SRC];
__device__ int   g_bsum[256];                  // block sums for scan (196 used)
__device__ int   g_sorted_src[N_EDGES];        // src index sorted by dst

// ---------------------------------------------------------------------------
// CSR construction: histogram -> scan -> fill
// ---------------------------------------------------------------------------
__global__ void zero_count_kernel() {
    int i = blockIdx.x * 256 + threadIdx.x;
    if (i < N_SRC) g_count[i] = 0;
    if (i == 0)    g_offset[N_SRC] = N_EDGES;
}

__global__ void hist_kernel(const int* __restrict__ dst_idx) {
    int e = blockIdx.x * 256 + threadIdx.x;
    if (e < N_EDGES) atomicAdd(&g_count[dst_idx[e]], 1);
}

__global__ void scan1_kernel() {
    __shared__ int sh[256];
    int t = threadIdx.x;
    int idx = blockIdx.x * 256 + t;
    int v = (idx < N_SRC) ? g_count[idx] : 0;
    sh[t] = v; __syncthreads();
    #pragma unroll
    for (int off = 1; off < 256; off <<= 1) {
        int x = (t >= off) ? sh[t - off] : 0;
        __syncthreads();
        sh[t] += x;
        __syncthreads();
    }
    if (idx < N_SRC) g_offset[idx] = sh[t] - v;       // exclusive within block
    if (t == 255)    g_bsum[blockIdx.x] = sh[255];    // block total
}

__global__ void scan2_kernel() {
    __shared__ int sh[256];
    int t = threadIdx.x;
    int v = (t < NBLK_N) ? g_bsum[t] : 0;
    sh[t] = v; __syncthreads();
    #pragma unroll
    for (int off = 1; off < 256; off <<= 1) {
        int x = (t >= off) ? sh[t - off] : 0;
        __syncthreads();
        sh[t] += x;
        __syncthreads();
    }
    if (t < NBLK_N) g_bsum[t] = sh[t] - v;            // exclusive block offsets
}

__global__ void scan3_kernel() {
    int i = blockIdx.x * 256 + threadIdx.x;
    if (i < N_SRC) {
        int o = g_offset[i] + g_bsum[blockIdx.x];
        g_offset[i] = o;
        g_cursor[i] = o;
    }
}

__global__ void fill_kernel(const int* __restrict__ src_idx,
                            const int* __restrict__ dst_idx) {
    int e = blockIdx.x * 256 + threadIdx.x;
    if (e < N_EDGES) {
        int pos = atomicAdd(&g_cursor[dst_idx[e]], 1);
        g_sorted_src[pos] = src_idx[e];
    }
}

// ---------------------------------------------------------------------------
// Gather-aggregate: one block (128 threads) per dst node. Each thread owns one
// float4 column; loops over that node's edges, sums, writes the row once.
// Writes zeros for degree-0 nodes, so no memset of g_agg is needed.
// ---------------------------------------------------------------------------
__global__ void __launch_bounds__(128) aggregate_kernel(
    const float* __restrict__ src_h)
{
    int d = blockIdx.x;
    int t = threadIdx.x;
    int start = g_offset[d];
    int end   = g_offset[d + 1];
    float4 acc = make_float4(0.f, 0.f, 0.f, 0.f);
    for (int j = start; j < end; j++) {
        int s = g_sorted_src[j];
        float4 v = reinterpret_cast<const float4*>(src_h + (size_t)s * D)[t];
        acc.x += v.x; acc.y += v.y; acc.z += v.z; acc.w += v.w;
    }
    reinterpret_cast<float4*>(g_agg + (size_t)d * D)[t] = acc;
}

// ---------------------------------------------------------------------------
// GEMM: out = agg @ W^T + b, TF32 mma.m16n8k8, 2-stage cp.async pipeline.
// BM=BN=128, BK=32, 256 threads (8 warps, warp tile 64x32).
// smem row stride 36 floats: 16B-aligned for cp.async AND conflict-free LDS
// (bank = (36*r + c) % 32 = (4g + t) distinct over the warp).
// ---------------------------------------------------------------------------
#define BM 128
#define BN 128
#define BK 32
#define LDT 36
#define STAGE_FLOATS (BM * LDT)
#define GEMM_SMEM_BYTES (4 * STAGE_FLOATS * 4)   // A[2] + B[2] = 73728 B

__device__ __forceinline__ unsigned f32_to_tf32(float f) {
    unsigned r;
    asm("cvt.rna.tf32.f32 %0, %1;" : "=r"(r) : "f"(f));
    return r;
}

__device__ __forceinline__ void mma_tf32_16x8x8(
    float d[4], const unsigned a[4], const unsigned b[2], const float c[4])
{
    asm volatile(
        "mma.sync.aligned.m16n8k8.row.col.f32.tf32.tf32.f32 "
        "{%0,%1,%2,%3}, {%4,%5,%6,%7}, {%8,%9}, {%10,%11,%12,%13};"
        : "=f"(d[0]), "=f"(d[1]), "=f"(d[2]), "=f"(d[3])
        : "r"(a[0]), "r"(a[1]), "r"(a[2]), "r"(a[3]),
          "r"(b[0]), "r"(b[1]),
          "f"(c[0]), "f"(c[1]), "f"(c[2]), "f"(c[3]));
}

__global__ void __launch_bounds__(256) gemm_kernel(
    const float* __restrict__ W,
    const float* __restrict__ bias,
    float*       __restrict__ out)
{
    extern __shared__ float smem[];
    float* As = smem;                       // [2][BM][LDT]
    float* Bs = smem + 2 * STAGE_FLOATS;    // [2][BN][LDT]

    const int tid  = threadIdx.x;
    const int warp = tid >> 5;
    const int lane = tid & 31;
    const int g    = lane >> 2;
    const int t    = lane & 3;

    const int wm = (warp & 1) * 64;
    const int wn = (warp >> 1) * 32;

    const int bm = blockIdx.y * BM;
    const int bn = blockIdx.x * BN;

    const int lr = tid >> 3;          // 0..31
    const int lc = (tid & 7) * 4;     // 0,4,...,28

    float acc[4][4][4];
    #pragma unroll
    for (int mt = 0; mt < 4; mt++)
        #pragma unroll
        for (int nt = 0; nt < 4; nt++)
            #pragma unroll
            for (int r = 0; r < 4; r++)
                acc[mt][nt][r] = 0.f;

    auto load_tiles = [&](int s, int k0) {
        #pragma unroll
        for (int i = 0; i < 4; i++) {
            int row  = lr + i * 32;
            int arow = bm + row;
            const float* ga = g_agg + (size_t)arow * D + k0 + lc;
            unsigned da = (unsigned)__cvta_generic_to_shared(
                              &As[s * STAGE_FLOATS + row * LDT + lc]);
            int szA = (arow < N_SRC) ? 16 : 0;   // zero-fill OOB rows
            asm volatile("cp.async.cg.shared.global [%0], [%1], 16, %2;"
                         :: "r"(da), "l"(ga), "r"(szA));
            const float* gb = W + (size_t)(bn + row) * D + k0 + lc;
            unsigned db = (unsigned)__cvta_generic_to_shared(
                              &Bs[s * STAGE_FLOATS + row * LDT + lc]);
            asm volatile("cp.async.cg.shared.global [%0], [%1], 16;"
                         :: "r"(db), "l"(gb));
        }
        asm volatile("cp.async.commit_group;");
    };

    const int NK = D / BK;   // 16
    load_tiles(0, 0);

    for (int ks = 0; ks < NK; ks++) {
        asm volatile("cp.async.wait_group 0;" ::: "memory");
        __syncthreads();
        if (ks + 1 < NK) load_tiles((ks + 1) & 1, (ks + 1) * BK);

        const float* A0 = &As[(ks & 1) * STAGE_FLOATS];
        const float* B0 = &Bs[(ks & 1) * STAGE_FLOATS];

        #pragma unroll
        for (int kk = 0; kk < BK; kk += 8) {
            unsigned afr[4][4];
            unsigned bfr[4][2];
            #pragma unroll
            for (int mt = 0; mt < 4; mt++) {
                int r = wm + mt * 16 + g;
                afr[mt][0] = f32_to_tf32(A0[ r      * LDT + kk + t    ]);
                afr[mt][1] = f32_to_tf32(A0[(r + 8) * LDT + kk + t    ]);
                afr[mt][2] = f32_to_tf32(A0[ r      * LDT + kk + t + 4]);
                afr[mt][3] = f32_to_tf32(A0[(r + 8) * LDT + kk + t + 4]);
            }
            #pragma unroll
            for (int nt = 0; nt < 4; nt++) {
                int c = wn + nt * 8 + g;
                bfr[nt][0] = f32_to_tf32(B0[c * LDT + kk + t    ]);
                bfr[nt][1] = f32_to_tf32(B0[c * LDT + kk + t + 4]);
            }
            #pragma unroll
            for (int mt = 0; mt < 4; mt++)
                #pragma unroll
                for (int nt = 0; nt < 4; nt++)
                    mma_tf32_16x8x8(acc[mt][nt], afr[mt], bfr[nt], acc[mt][nt]);
        }
        __syncthreads();
    }

    // Epilogue: add bias, store
    #pragma unroll
    for (int mt = 0; mt < 4; mt++) {
        #pragma unroll
        for (int nt = 0; nt < 4; nt++) {
            int row0 = bm + wm + mt * 16 + g;
            int row1 = row0 + 8;
            int col  = bn + wn + nt * 8 + 2 * t;
            float b0 = __ldg(bias + col);
            float b1 = __ldg(bias + col + 1);
            if (row0 < N_SRC) {
                out[(size_t)row0 * D + col    ] = acc[mt][nt][0] + b0;
                out[(size_t)row0 * D + col + 1] = acc[mt][nt][1] + b1;
            }
            if (row1 < N_SRC) {
                out[(size_t)row1 * D + col    ] = acc[mt][nt][2] + b0;
                out[(size_t)row1 * D + col + 1] = acc[mt][nt][3] + b1;
            }
        }
    }
}

// ---------------------------------------------------------------------------
// Launch. Inputs per metadata order:
//   0: src_h [50000,512] f32   1: W [512,512] f32   2: b [512] f32
//   3: src_idx [150000] i32    4: dst_idx [150000] i32   5: n_dst scalar
// ---------------------------------------------------------------------------
extern "C" void kernel_launch(void* const* d_in, const int* in_sizes, int n_in,
                              void* d_out, int out_size)
{
    const float* src_h   = (const float*)d_in[0];
    const float* W       = (const float*)d_in[1];
    const float* bias    = (const float*)d_in[2];
    const int*   src_idx = (const int*)d_in[3];
    const int*   dst_idx = (const int*)d_in[4];
    float*       out     = (float*)d_out;

    cudaFuncSetAttribute(gemm_kernel,
                         cudaFuncAttributeMaxDynamicSharedMemorySize,
                         GEMM_SMEM_BYTES);

    zero_count_kernel<<<NBLK_N, 256>>>();
    hist_kernel<<<NBLK_E, 256>>>(dst_idx);
    scan1_kernel<<<NBLK_N, 256>>>();
    scan2_kernel<<<1, 256>>>();
    scan3_kernel<<<NBLK_N, 256>>>();
    fill_kernel<<<NBLK_E, 256>>>(src_idx, dst_idx);
    aggregate_kernel<<<N_SRC, 128>>>(src_h);

    dim3 grid(D / BN, (N_SRC + BM - 1) / BM);   // (4, 391)
    gemm_kernel<<<grid, 256, GEMM_SMEM_BYTES>>>(W, bias, out);
}

// round 6
// speedup vs baseline: 1.8296x; 1.0321x over previous
#include <cuda_runtime.h>
#include <cstdint>

// Problem constants (fixed by the dataset)
#define N_SRC   50000
#define N_EDGES 150000
#define D       512
#define NBLK_N  196          // ceil(N_SRC / 256)
#define NBLK_E  587          // ceil(N_EDGES / 256)

// ---------------------------------------------------------------------------
// Device scratch (no allocations allowed)
// ---------------------------------------------------------------------------
__device__ float g_agg[(size_t)N_SRC * D];     // aggregated messages (tf32-rounded)
__device__ float g_Wr[(size_t)D * D];          // W rounded to tf32
__device__ int   g_count[N_SRC];
__device__ int   g_offset[N_SRC + 1];
__device__ int   g_cursor[N_SRC];
__device__ int   g_bsum[256];
__device__ int   g_sorted_src[N_EDGES];

__device__ __forceinline__ unsigned f32_to_tf32(float f) {
    unsigned r;
    asm("cvt.rna.tf32.f32 %0, %1;" : "=r"(r) : "f"(f));
    return r;
}

__device__ __forceinline__ void mma_tf32_16x8x8(
    float d[4], const unsigned a[4], const unsigned b[2], const float c[4])
{
    asm volatile(
        "mma.sync.aligned.m16n8k8.row.col.f32.tf32.tf32.f32 "
        "{%0,%1,%2,%3}, {%4,%5,%6,%7}, {%8,%9}, {%10,%11,%12,%13};"
        : "=f"(d[0]), "=f"(d[1]), "=f"(d[2]), "=f"(d[3])
        : "r"(a[0]), "r"(a[1]), "r"(a[2]), "r"(a[3]),
          "r"(b[0]), "r"(b[1]),
          "f"(c[0]), "f"(c[1]), "f"(c[2]), "f"(c[3]));
}

// ---------------------------------------------------------------------------
// CSR construction: histogram -> scan -> fill.  (zero+roundW merged)
// ---------------------------------------------------------------------------
__global__ void zero_and_roundw_kernel(const float* __restrict__ W) {
    int i = blockIdx.x * 256 + threadIdx.x;
    if (i < N_SRC) g_count[i] = 0;
    if (i == 0)    g_offset[N_SRC] = N_EDGES;
    // W has 65536 float4s; NBLK_N*256 = 50176 threads -> strided x2
    for (int j = i; j < (D * D) / 4; j += NBLK_N * 256) {
        float4 v = reinterpret_cast<const float4*>(W)[j];
        float4 r;
        r.x = __uint_as_float(f32_to_tf32(v.x));
        r.y = __uint_as_float(f32_to_tf32(v.y));
        r.z = __uint_as_float(f32_to_tf32(v.z));
        r.w = __uint_as_float(f32_to_tf32(v.w));
        reinterpret_cast<float4*>(g_Wr)[j] = r;
    }
}

__global__ void hist_kernel(const int* __restrict__ dst_idx) {
    int e = blockIdx.x * 256 + threadIdx.x;
    if (e < N_EDGES) atomicAdd(&g_count[dst_idx[e]], 1);
}

__global__ void scan1_kernel() {
    __shared__ int sh[256];
    int t = threadIdx.x;
    int idx = blockIdx.x * 256 + t;
    int v = (idx < N_SRC) ? g_count[idx] : 0;
    sh[t] = v; __syncthreads();
    #pragma unroll
    for (int off = 1; off < 256; off <<= 1) {
        int x = (t >= off) ? sh[t - off] : 0;
        __syncthreads();
        sh[t] += x;
        __syncthreads();
    }
    if (idx < N_SRC) g_offset[idx] = sh[t] - v;
    if (t == 255)    g_bsum[blockIdx.x] = sh[255];
}

__global__ void scan2_kernel() {
    __shared__ int sh[256];
    int t = threadIdx.x;
    int v = (t < NBLK_N) ? g_bsum[t] : 0;
    sh[t] = v; __syncthreads();
    #pragma unroll
    for (int off = 1; off < 256; off <<= 1) {
        int x = (t >= off) ? sh[t - off] : 0;
        __syncthreads();
        sh[t] += x;
        __syncthreads();
    }
    if (t < NBLK_N) g_bsum[t] = sh[t] - v;
}

__global__ void scan3_kernel() {
    int i = blockIdx.x * 256 + threadIdx.x;
    if (i < N_SRC) {
        int o = g_offset[i] + g_bsum[blockIdx.x];
        g_offset[i] = o;
        g_cursor[i] = o;
    }
}

__global__ void fill_kernel(const int* __restrict__ src_idx,
                            const int* __restrict__ dst_idx) {
    int e = blockIdx.x * 256 + threadIdx.x;
    if (e < N_EDGES) {
        int pos = atomicAdd(&g_cursor[dst_idx[e]], 1);
        g_sorted_src[pos] = src_idx[e];
    }
}

// ---------------------------------------------------------------------------
// Gather-aggregate: one block (128 threads) per dst node; writes tf32-rounded
// rows (so the GEMM needs no per-fragment cvt).
// ---------------------------------------------------------------------------
__global__ void __launch_bounds__(128) aggregate_kernel(
    const float* __restrict__ src_h)
{
    int d = blockIdx.x;
    int t = threadIdx.x;
    int start = g_offset[d];
    int end   = g_offset[d + 1];
    float4 acc = make_float4(0.f, 0.f, 0.f, 0.f);
    for (int j = start; j < end; j++) {
        int s = g_sorted_src[j];
        float4 v = reinterpret_cast<const float4*>(src_h + (size_t)s * D)[t];
        acc.x += v.x; acc.y += v.y; acc.z += v.z; acc.w += v.w;
    }
    float4 r;
    r.x = __uint_as_float(f32_to_tf32(acc.x));
    r.y = __uint_as_float(f32_to_tf32(acc.y));
    r.z = __uint_as_float(f32_to_tf32(acc.z));
    r.w = __uint_as_float(f32_to_tf32(acc.w));
    reinterpret_cast<float4*>(g_agg + (size_t)d * D)[t] = r;
}

// ---------------------------------------------------------------------------
// GEMM: out = agg @ W^T + b, TF32 mma.m16n8k8, 2-stage cp.async pipeline.
// BM=128, BN=256, BK=32; 256 threads (8 warps as 2x4, warp tile 64x64).
// smem row stride 36 floats: 16B-aligned for cp.async, conflict-free LDS.
// Data is pre-rounded to tf32 in memory -> fragments load raw bits (no cvt).
// ---------------------------------------------------------------------------
#define BM 128
#define BN 256
#define BK 32
#define LDT 36
#define A_STAGE (BM * LDT)                 // 4608 floats
#define B_STAGE (BN * LDT)                 // 9216 floats
#define STAGE_FLOATS (A_STAGE + B_STAGE)   // 13824 floats
#define GEMM_SMEM_BYTES (2 * STAGE_FLOATS * 4)   // 110592 B

__global__ void __launch_bounds__(256, 1) gemm_kernel(
    const float* __restrict__ bias,
    float*       __restrict__ out)
{
    extern __shared__ float smem[];

    const int tid  = threadIdx.x;
    const int warp = tid >> 5;
    const int lane = tid & 31;
    const int g    = lane >> 2;   // 0..7
    const int t    = lane & 3;    // 0..3

    const int wm = (warp & 1) * 64;    // 2 warps along M
    const int wn = (warp >> 1) * 64;   // 4 warps along N

    const int bm = blockIdx.y * BM;
    const int bn = blockIdx.x * BN;

    const int lr = tid >> 3;          // 0..31
    const int lc = (tid & 7) * 4;     // 0,4,...,28

    float acc[4][8][4];
    #pragma unroll
    for (int mt = 0; mt < 4; mt++)
        #pragma unroll
        for (int nt = 0; nt < 8; nt++)
            #pragma unroll
            for (int r = 0; r < 4; r++)
                acc[mt][nt][r] = 0.f;

    auto load_tiles = [&](int s, int k0) {
        float* As = smem + s * STAGE_FLOATS;
        float* Bs = As + A_STAGE;
        // A: 128 rows -> 4 passes of 32 rows
        #pragma unroll
        for (int i = 0; i < 4; i++) {
            int row  = lr + i * 32;
            int arow = bm + row;
            const float* ga = g_agg + (size_t)arow * D + k0 + lc;
            unsigned da = (unsigned)__cvta_generic_to_shared(&As[row * LDT + lc]);
            int sz = (arow < N_SRC) ? 16 : 0;   // zero-fill OOB rows
            asm volatile("cp.async.cg.shared.global [%0], [%1], 16, %2;"
                         :: "r"(da), "l"(ga), "r"(sz));
        }
        // B: 256 rows -> 8 passes of 32 rows (always in-bounds)
        #pragma unroll
        for (int i = 0; i < 8; i++) {
            int row = lr + i * 32;
            const float* gb = g_Wr + (size_t)(bn + row) * D + k0 + lc;
            unsigned db = (unsigned)__cvta_generic_to_shared(&Bs[row * LDT + lc]);
            asm volatile("cp.async.cg.shared.global [%0], [%1], 16;"
                         :: "r"(db), "l"(gb));
        }
        asm volatile("cp.async.commit_group;");
    };

    const int NK = D / BK;   // 16
    load_tiles(0, 0);

    for (int ks = 0; ks < NK; ks++) {
        asm volatile("cp.async.wait_group 0;" ::: "memory");
        __syncthreads();
        if (ks + 1 < NK) load_tiles((ks + 1) & 1, (ks + 1) * BK);

        const unsigned* A0 = reinterpret_cast<const unsigned*>(
                                 smem + (ks & 1) * STAGE_FLOATS);
        const unsigned* B0 = A0 + A_STAGE;

        #pragma unroll
        for (int kk = 0; kk < BK; kk += 8) {
            unsigned afr[4][4];
            unsigned bfr[8][2];
            #pragma unroll
            for (int mt = 0; mt < 4; mt++) {
                int r = wm + mt * 16 + g;
                afr[mt][0] = A0[ r      * LDT + kk + t    ];
                afr[mt][1] = A0[(r + 8) * LDT + kk + t    ];
                afr[mt][2] = A0[ r      * LDT + kk + t + 4];
                afr[mt][3] = A0[(r + 8) * LDT + kk + t + 4];
            }
            #pragma unroll
            for (int nt = 0; nt < 8; nt++) {
                int c = wn + nt * 8 + g;
                bfr[nt][0] = B0[c * LDT + kk + t    ];
                bfr[nt][1] = B0[c * LDT + kk + t + 4];
            }
            #pragma unroll
            for (int mt = 0; mt < 4; mt++)
                #pragma unroll
                for (int nt = 0; nt < 8; nt++)
                    mma_tf32_16x8x8(acc[mt][nt], afr[mt], bfr[nt], acc[mt][nt]);
        }
        __syncthreads();
    }

    // Epilogue: add bias, store
    #pragma unroll
    for (int mt = 0; mt < 4; mt++) {
        int row0 = bm + wm + mt * 16 + g;
        int row1 = row0 + 8;
        #pragma unroll
        for (int nt = 0; nt < 8; nt++) {
            int col = bn + wn + nt * 8 + 2 * t;
            float b0 = __ldg(bias + col);
            float b1 = __ldg(bias + col + 1);
            if (row0 < N_SRC) {
                out[(size_t)row0 * D + col    ] = acc[mt][nt][0] + b0;
                out[(size_t)row0 * D + col + 1] = acc[mt][nt][1] + b1;
            }
            if (row1 < N_SRC) {
                out[(size_t)row1 * D + col    ] = acc[mt][nt][2] + b0;
                out[(size_t)row1 * D + col + 1] = acc[mt][nt][3] + b1;
            }
        }
    }
}

// ---------------------------------------------------------------------------
// Launch. Inputs per metadata order:
//   0: src_h [50000,512] f32   1: W [512,512] f32   2: b [512] f32
//   3: src_idx [150000] i32    4: dst_idx [150000] i32   5: n_dst scalar
// ---------------------------------------------------------------------------
extern "C" void kernel_launch(void* const* d_in, const int* in_sizes, int n_in,
                              void* d_out, int out_size)
{
    const float* src_h   = (const float*)d_in[0];
    const float* W       = (const float*)d_in[1];
    const float* bias    = (const float*)d_in[2];
    const int*   src_idx = (const int*)d_in[3];
    const int*   dst_idx = (const int*)d_in[4];
    float*       out     = (float*)d_out;

    cudaFuncSetAttribute(gemm_kernel,
                         cudaFuncAttributeMaxDynamicSharedMemorySize,
                         GEMM_SMEM_BYTES);

    zero_and_roundw_kernel<<<NBLK_N, 256>>>(W);
    hist_kernel<<<NBLK_E, 256>>>(dst_idx);
    scan1_kernel<<<NBLK_N, 256>>>();
    scan2_kernel<<<1, 256>>>();
    scan3_kernel<<<NBLK_N, 256>>>();
    fill_kernel<<<NBLK_E, 256>>>(src_idx, dst_idx);
    aggregate_kernel<<<N_SRC, 128>>>(src_h);

    dim3 grid(D / BN, (N_SRC + BM - 1) / BM);   // (2, 391)
    gemm_kernel<<<grid, 256, GEMM_SMEM_BYTES>>>(bias, out);
}

// round 7
// speedup vs baseline: 2.4295x; 1.3279x over previous
#include <cuda_runtime.h>
#include <cuda_fp16.h>
#include <cstdint>

// Problem constants (fixed by the dataset)
#define N_SRC   50000
#define N_EDGES 150000
#define D       512
#define NBLK_N  196          // ceil(N_SRC / 256)
#define NBLK_E  587          // ceil(N_EDGES / 256)

// ---------------------------------------------------------------------------
// Device scratch (no allocations allowed)
// ---------------------------------------------------------------------------
__device__ __half g_aggh[(size_t)N_SRC * D];   // aggregated messages (fp16)
__device__ __half g_Wh[(size_t)D * D];         // W rounded to fp16
__device__ int    g_count[N_SRC];
__device__ int    g_offset[N_SRC + 1];
__device__ int    g_cursor[N_SRC];
__device__ int    g_bsum[256];
__device__ int    g_sorted_src[N_EDGES];

__device__ __forceinline__ void mma_f16_16x8x16(
    float d[4], const unsigned a[4], const unsigned b[2], const float c[4])
{
    asm volatile(
        "mma.sync.aligned.m16n8k16.row.col.f32.f16.f16.f32 "
        "{%0,%1,%2,%3}, {%4,%5,%6,%7}, {%8,%9}, {%10,%11,%12,%13};"
        : "=f"(d[0]), "=f"(d[1]), "=f"(d[2]), "=f"(d[3])
        : "r"(a[0]), "r"(a[1]), "r"(a[2]), "r"(a[3]),
          "r"(b[0]), "r"(b[1]),
          "f"(c[0]), "f"(c[1]), "f"(c[2]), "f"(c[3]));
}

// ---------------------------------------------------------------------------
// CSR construction: histogram -> scan -> fill.  (zero+roundW merged)
// ---------------------------------------------------------------------------
__global__ void zero_and_roundw_kernel(const float* __restrict__ W) {
    int i = blockIdx.x * 256 + threadIdx.x;
    if (i < N_SRC) g_count[i] = 0;
    if (i == 0)    g_offset[N_SRC] = N_EDGES;
    // W has 65536 float4s; NBLK_N*256 = 50176 threads -> strided x2
    for (int j = i; j < (D * D) / 4; j += NBLK_N * 256) {
        float4 v = reinterpret_cast<const float4*>(W)[j];
        __half2 h0 = __floats2half2_rn(v.x, v.y);
        __half2 h1 = __floats2half2_rn(v.z, v.w);
        uint2 u;
        u.x = *reinterpret_cast<unsigned*>(&h0);
        u.y = *reinterpret_cast<unsigned*>(&h1);
        reinterpret_cast<uint2*>(g_Wh)[j] = u;
    }
}

__global__ void hist_kernel(const int* __restrict__ dst_idx) {
    int e = blockIdx.x * 256 + threadIdx.x;
    if (e < N_EDGES) atomicAdd(&g_count[dst_idx[e]], 1);
}

__global__ void scan1_kernel() {
    __shared__ int sh[256];
    int t = threadIdx.x;
    int idx = blockIdx.x * 256 + t;
    int v = (idx < N_SRC) ? g_count[idx] : 0;
    sh[t] = v; __syncthreads();
    #pragma unroll
    for (int off = 1; off < 256; off <<= 1) {
        int x = (t >= off) ? sh[t - off] : 0;
        __syncthreads();
        sh[t] += x;
        __syncthreads();
    }
    if (idx < N_SRC) g_offset[idx] = sh[t] - v;
    if (t == 255)    g_bsum[blockIdx.x] = sh[255];
}

__global__ void scan2_kernel() {
    __shared__ int sh[256];
    int t = threadIdx.x;
    int v = (t < NBLK_N) ? g_bsum[t] : 0;
    sh[t] = v; __syncthreads();
    #pragma unroll
    for (int off = 1; off < 256; off <<= 1) {
        int x = (t >= off) ? sh[t - off] : 0;
        __syncthreads();
        sh[t] += x;
        __syncthreads();
    }
    if (t < NBLK_N) g_bsum[t] = sh[t] - v;
}

__global__ void scan3_kernel() {
    int i = blockIdx.x * 256 + threadIdx.x;
    if (i < N_SRC) {
        int o = g_offset[i] + g_bsum[blockIdx.x];
        g_offset[i] = o;
        g_cursor[i] = o;
    }
}

__global__ void fill_kernel(const int* __restrict__ src_idx,
                            const int* __restrict__ dst_idx) {
    int e = blockIdx.x * 256 + threadIdx.x;
    if (e < N_EDGES) {
        int pos = atomicAdd(&g_cursor[dst_idx[e]], 1);
        g_sorted_src[pos] = src_idx[e];
    }
}

// ---------------------------------------------------------------------------
// Gather-aggregate: one block (128 threads) per dst node; accumulate in fp32,
// write fp16 rows (halves GEMM input traffic; eps(fp16)=eps(tf32)=2^-11).
// ---------------------------------------------------------------------------
__global__ void __launch_bounds__(128) aggregate_kernel(
    const float* __restrict__ src_h)
{
    int d = blockIdx.x;
    int t = threadIdx.x;
    int start = g_offset[d];
    int end   = g_offset[d + 1];
    float4 acc = make_float4(0.f, 0.f, 0.f, 0.f);
    for (int j = start; j < end; j++) {
        int s = g_sorted_src[j];
        float4 v = reinterpret_cast<const float4*>(src_h + (size_t)s * D)[t];
        acc.x += v.x; acc.y += v.y; acc.z += v.z; acc.w += v.w;
    }
    __half2 h0 = __floats2half2_rn(acc.x, acc.y);
    __half2 h1 = __floats2half2_rn(acc.z, acc.w);
    uint2 u;
    u.x = *reinterpret_cast<unsigned*>(&h0);
    u.y = *reinterpret_cast<unsigned*>(&h1);
    reinterpret_cast<uint2*>(g_aggh + (size_t)d * D)[t] = u;
}

// ---------------------------------------------------------------------------
// GEMM: out = agg @ W^T + b, FP16 mma.m16n8k16 (f32 accum), 2-stage cp.async.
// BM=128, BN=256, BK=32 halves; 256 threads (8 warps as 2x4, warp tile 64x64).
// smem row stride 40 halves (80B): 16B-aligned for cp.async; fragment b32
// LDS pattern (r*20 + t) mod 32 is a permutation -> conflict-free.
// ---------------------------------------------------------------------------
#define BM 128
#define BN 256
#define BK 32                               // K elements (halves) per tile
#define LDT 40                              // halves per smem row
#define A_STAGE (BM * LDT)                  // 5120 halves
#define B_STAGE (BN * LDT)                  // 10240 halves
#define STAGE_HALVES (A_STAGE + B_STAGE)    // 15360 halves
#define GEMM_SMEM_BYTES (2 * STAGE_HALVES * 2)   // 61440 B

__global__ void __launch_bounds__(256, 1) gemm_kernel(
    const float* __restrict__ bias,
    float*       __restrict__ out)
{
    extern __shared__ __half smem[];

    const int tid  = threadIdx.x;
    const int warp = tid >> 5;
    const int lane = tid & 31;
    const int g    = lane >> 2;   // 0..7
    const int t    = lane & 3;    // 0..3

    const int wm = (warp & 1) * 64;    // 2 warps along M
    const int wn = (warp >> 1) * 64;   // 4 warps along N

    const int bm = blockIdx.y * BM;
    const int bn = blockIdx.x * BN;

    // Tile-load indexing: 16B chunk = 8 halves; 4 chunks per row (BK=32).
    const int chunk = (tid & 3) * 8;      // half offset within row: 0,8,16,24
    const int rowb  = tid >> 2;           // 0..63

    float acc[4][8][4];
    #pragma unroll
    for (int mt = 0; mt < 4; mt++)
        #pragma unroll
        for (int nt = 0; nt < 8; nt++)
            #pragma unroll
            for (int r = 0; r < 4; r++)
                acc[mt][nt][r] = 0.f;

    auto load_tiles = [&](int s, int k0) {
        __half* As = smem + s * STAGE_HALVES;
        __half* Bs = As + A_STAGE;
        // A: 128 rows -> 2 passes of 64 rows
        #pragma unroll
        for (int i = 0; i < 2; i++) {
            int row  = rowb + i * 64;
            int arow = bm + row;
            const __half* ga = g_aggh + (size_t)arow * D + k0 + chunk;
            unsigned da = (unsigned)__cvta_generic_to_shared(&As[row * LDT + chunk]);
            int sz = (arow < N_SRC) ? 16 : 0;   // zero-fill OOB rows
            asm volatile("cp.async.cg.shared.global [%0], [%1], 16, %2;"
                         :: "r"(da), "l"(ga), "r"(sz));
        }
        // B: 256 rows -> 4 passes of 64 rows (always in-bounds)
        #pragma unroll
        for (int i = 0; i < 4; i++) {
            int row = rowb + i * 64;
            const __half* gb = g_Wh + (size_t)(bn + row) * D + k0 + chunk;
            unsigned db = (unsigned)__cvta_generic_to_shared(&Bs[row * LDT + chunk]);
            asm volatile("cp.async.cg.shared.global [%0], [%1], 16;"
                         :: "r"(db), "l"(gb));
        }
        asm volatile("cp.async.commit_group;");
    };

    const int NK = D / BK;   // 16
    load_tiles(0, 0);

    for (int ks = 0; ks < NK; ks++) {
        asm volatile("cp.async.wait_group 0;" ::: "memory");
        __syncthreads();
        if (ks + 1 < NK) load_tiles((ks + 1) & 1, (ks + 1) * BK);

        const __half* A0 = smem + (ks & 1) * STAGE_HALVES;
        const __half* B0 = A0 + A_STAGE;

        #pragma unroll
        for (int kk = 0; kk < BK; kk += 16) {   // 2 x K16 steps
            unsigned afr[4][4];
            unsigned bfr[8][2];
            #pragma unroll
            for (int mt = 0; mt < 4; mt++) {
                int r = wm + mt * 16 + g;
                afr[mt][0] = *reinterpret_cast<const unsigned*>(&A0[ r      * LDT + kk + 2 * t    ]);
                afr[mt][1] = *reinterpret_cast<const unsigned*>(&A0[(r + 8) * LDT + kk + 2 * t    ]);
                afr[mt][2] = *reinterpret_cast<const unsigned*>(&A0[ r      * LDT + kk + 2 * t + 8]);
                afr[mt][3] = *reinterpret_cast<const unsigned*>(&A0[(r + 8) * LDT + kk + 2 * t + 8]);
            }
            #pragma unroll
            for (int nt = 0; nt < 8; nt++) {
                int c = wn + nt * 8 + g;
                bfr[nt][0] = *reinterpret_cast<const unsigned*>(&B0[c * LDT + kk + 2 * t    ]);
                bfr[nt][1] = *reinterpret_cast<const unsigned*>(&B0[c * LDT + kk + 2 * t + 8]);
            }
            #pragma unroll
            for (int mt = 0; mt < 4; mt++)
                #pragma unroll
                for (int nt = 0; nt < 8; nt++)
                    mma_f16_16x8x16(acc[mt][nt], afr[mt], bfr[nt], acc[mt][nt]);
        }
        __syncthreads();
    }

    // Epilogue: add bias, store
    #pragma unroll
    for (int mt = 0; mt < 4; mt++) {
        int row0 = bm + wm + mt * 16 + g;
        int row1 = row0 + 8;
        #pragma unroll
        for (int nt = 0; nt < 8; nt++) {
            int col = bn + wn + nt * 8 + 2 * t;
            float b0 = __ldg(bias + col);
            float b1 = __ldg(bias + col + 1);
            if (row0 < N_SRC) {
                out[(size_t)row0 * D + col    ] = acc[mt][nt][0] + b0;
                out[(size_t)row0 * D + col + 1] = acc[mt][nt][1] + b1;
            }
            if (row1 < N_SRC) {
                out[(size_t)row1 * D + col    ] = acc[mt][nt][2] + b0;
                out[(size_t)row1 * D + col + 1] = acc[mt][nt][3] + b1;
            }
        }
    }
}

// ---------------------------------------------------------------------------
// Launch. Inputs per metadata order:
//   0: src_h [50000,512] f32   1: W [512,512] f32   2: b [512] f32
//   3: src_idx [150000] i32    4: dst_idx [150000] i32   5: n_dst scalar
// ---------------------------------------------------------------------------
extern "C" void kernel_launch(void* const* d_in, const int* in_sizes, int n_in,
                              void* d_out, int out_size)
{
    const float* src_h   = (const float*)d_in[0];
    const float* W       = (const float*)d_in[1];
    const float* bias    = (const float*)d_in[2];
    const int*   src_idx = (const int*)d_in[3];
    const int*   dst_idx = (const int*)d_in[4];
    float*       out     = (float*)d_out;

    cudaFuncSetAttribute(gemm_kernel,
                         cudaFuncAttributeMaxDynamicSharedMemorySize,
                         GEMM_SMEM_BYTES);

    zero_and_roundw_kernel<<<NBLK_N, 256>>>(W);
    hist_kernel<<<NBLK_E, 256>>>(dst_idx);
    scan1_kernel<<<NBLK_N, 256>>>();
    scan2_kernel<<<1, 256>>>();
    scan3_kernel<<<NBLK_N, 256>>>();
    fill_kernel<<<NBLK_E, 256>>>(src_idx, dst_idx);
    aggregate_kernel<<<N_SRC, 128>>>(src_h);

    dim3 grid(D / BN, (N_SRC + BM - 1) / BM);   // (2, 391)
    gemm_kernel<<<grid, 256, GEMM_SMEM_BYTES>>>(bias, out);
}

// round 9
// speedup vs baseline: 2.8877x; 1.1886x over previous
#include <cuda_runtime.h>
#include <cuda_fp16.h>
#include <cstdint>

// Problem constants (fixed by the dataset)
#define N_SRC   50000
#define N_EDGES 150000
#define D       512
#define NBLK_N  196          // ceil(N_SRC / 256)
#define NBLK_E  587          // ceil(N_EDGES / 256)

// ---------------------------------------------------------------------------
// Device scratch (no allocations allowed)
// ---------------------------------------------------------------------------
__device__ __half g_srch[(size_t)N_SRC * D];   // src_h converted to fp16 (51 MB)
__device__ __half g_aggh[(size_t)N_SRC * D];   // aggregated messages (fp16)
__device__ __half g_Wh[(size_t)D * D];         // W rounded to fp16
__device__ int    g_count[N_SRC];
__device__ int    g_offset[N_SRC + 1];
__device__ int    g_cursor[N_SRC];
__device__ int    g_bsum[256];
__device__ int    g_sorted_src[N_EDGES];

__device__ __forceinline__ void mma_f16_16x8x16(
    float d[4], const unsigned a[4], const unsigned b[2], const float c[4])
{
    asm volatile(
        "mma.sync.aligned.m16n8k16.row.col.f32.f16.f16.f32 "
        "{%0,%1,%2,%3}, {%4,%5,%6,%7}, {%8,%9}, {%10,%11,%12,%13};"
        : "=f"(d[0]), "=f"(d[1]), "=f"(d[2]), "=f"(d[3])
        : "r"(a[0]), "r"(a[1]), "r"(a[2]), "r"(a[3]),
          "r"(b[0]), "r"(b[1]),
          "f"(c[0]), "f"(c[1]), "f"(c[2]), "f"(c[3]));
}

__device__ __forceinline__ void ldsm_x4(unsigned r[4], unsigned addr) {
    asm volatile("ldmatrix.sync.aligned.m8n8.x4.shared.b16 {%0,%1,%2,%3}, [%4];"
                 : "=r"(r[0]), "=r"(r[1]), "=r"(r[2]), "=r"(r[3]) : "r"(addr));
}

// ---------------------------------------------------------------------------
// Prep kernel: zero counts, round W to fp16, convert src_h to fp16.
// ---------------------------------------------------------------------------
#define PREP_BLOCKS 512
__global__ void prep_kernel(const float* __restrict__ W,
                            const float* __restrict__ src_h) {
    int i = blockIdx.x * 256 + threadIdx.x;
    int nthreads = PREP_BLOCKS * 256;
    for (int j = i; j < N_SRC; j += nthreads) g_count[j] = 0;
    if (i == 0) g_offset[N_SRC] = N_EDGES;
    // W: 65536 float4s -> fp16
    for (int j = i; j < (D * D) / 4; j += nthreads) {
        float4 v = reinterpret_cast<const float4*>(W)[j];
        __half2 h0 = __floats2half2_rn(v.x, v.y);
        __half2 h1 = __floats2half2_rn(v.z, v.w);
        uint2 u;
        u.x = *reinterpret_cast<unsigned*>(&h0);
        u.y = *reinterpret_cast<unsigned*>(&h1);
        reinterpret_cast<uint2*>(g_Wh)[j] = u;
    }
    // src_h: 6.4M float4s -> fp16
    for (int j = i; j < (N_SRC * D) / 4; j += nthreads) {
        float4 v = reinterpret_cast<const float4*>(src_h)[j];
        __half2 h0 = __floats2half2_rn(v.x, v.y);
        __half2 h1 = __floats2half2_rn(v.z, v.w);
        uint2 u;
        u.x = *reinterpret_cast<unsigned*>(&h0);
        u.y = *reinterpret_cast<unsigned*>(&h1);
        reinterpret_cast<uint2*>(g_srch)[j] = u;
    }
}

__global__ void hist_kernel(const int* __restrict__ dst_idx) {
    int e = blockIdx.x * 256 + threadIdx.x;
    if (e < N_EDGES) atomicAdd(&g_count[dst_idx[e]], 1);
}

__global__ void scan1_kernel() {
    __shared__ int sh[256];
    int t = threadIdx.x;
    int idx = blockIdx.x * 256 + t;
    int v = (idx < N_SRC) ? g_count[idx] : 0;
    sh[t] = v; __syncthreads();
    #pragma unroll
    for (int off = 1; off < 256; off <<= 1) {
        int x = (t >= off) ? sh[t - off] : 0;
        __syncthreads();
        sh[t] += x;
        __syncthreads();
    }
    if (idx < N_SRC) g_offset[idx] = sh[t] - v;
    if (t == 255)    g_bsum[blockIdx.x] = sh[255];
}

// scan3 with integrated block-sum prefix (replaces scan2+scan3)
__global__ void scan3_kernel() {
    __shared__ int s_base;
    int t = threadIdx.x;
    if (t == 0) s_base = 0;
    __syncthreads();
    int partial = 0;
    for (int j = t; j < blockIdx.x; j += 256) partial += g_bsum[j];
    if (partial) atomicAdd(&s_base, partial);
    __syncthreads();
    int i = blockIdx.x * 256 + t;
    if (i < N_SRC) {
        int o = g_offset[i] + s_base;
        g_offset[i] = o;
        g_cursor[i] = o;
    }
}

__global__ void fill_kernel(const int* __restrict__ src_idx,
                            const int* __restrict__ dst_idx) {
    int e = blockIdx.x * 256 + threadIdx.x;
    if (e < N_EDGES) {
        int pos = atomicAdd(&g_cursor[dst_idx[e]], 1);
        g_sorted_src[pos] = src_idx[e];
    }
}

// ---------------------------------------------------------------------------
// Gather-aggregate: one block (128 threads) per dst node; fp16 gather,
// fp32 accumulate, fp16 write.
// ---------------------------------------------------------------------------
__global__ void __launch_bounds__(128) aggregate_kernel()
{
    int d = blockIdx.x;
    int t = threadIdx.x;                 // 0..127 -> 4 halves each (uint2)
    int start = g_offset[d];
    int end   = g_offset[d + 1];
    float ax = 0.f, ay = 0.f, az = 0.f, aw = 0.f;
    for (int j = start; j < end; j++) {
        int s = g_sorted_src[j];
        uint2 u = reinterpret_cast<const uint2*>(g_srch + (size_t)s * D)[t];
        __half2 h0 = *reinterpret_cast<__half2*>(&u.x);
        __half2 h1 = *reinterpret_cast<__half2*>(&u.y);
        float2 f0 = __half22float2(h0);
        float2 f1 = __half22float2(h1);
        ax += f0.x; ay += f0.y; az += f1.x; aw += f1.y;
    }
    __half2 h0 = __floats2half2_rn(ax, ay);
    __half2 h1 = __floats2half2_rn(az, aw);
    uint2 u;
    u.x = *reinterpret_cast<unsigned*>(&h0);
    u.y = *reinterpret_cast<unsigned*>(&h1);
    reinterpret_cast<uint2*>(g_aggh + (size_t)d * D)[t] = u;
}

// ---------------------------------------------------------------------------
// GEMM: out = agg @ W^T + b, FP16 mma.m16n8k16 (f32 accum).
// BM=128, BN=128, BK=64 halves; 256 threads, 8 warps (4M x 2N), warp 32x64.
// 2 CTAs/SM (launch_bounds(256,2)), 2-stage cp.async, ldmatrix fragments.
// smem row stride 72 halves (144B): 16B-aligned, ldmatrix conflict-free
// (row-to-row bank shift of 16B covers 8 distinct 16B lanes).
// ---------------------------------------------------------------------------
#define BM 128
#define BN 128
#define BK 64
#define LDT 72
#define A_BYTES (BM * LDT * 2)              // 18432
#define STAGE_BYTES (2 * A_BYTES)           // A + B = 36864
#define GEMM_SMEM_BYTES (2 * STAGE_BYTES)   // 73728

__global__ void __launch_bounds__(256, 2) gemm_kernel(
    const float* __restrict__ bias,
    float*       __restrict__ out)
{
    extern __shared__ __half smem[];
    uint32_t smem_b;
    {
        uint64_t tmp = __cvta_generic_to_shared(smem);
        smem_b = (uint32_t)tmp;
    }

    const int tid  = threadIdx.x;
    const int warp = tid >> 5;
    const int lane = tid & 31;
    const int g    = lane >> 2;   // 0..7
    const int t    = lane & 3;    // 0..3

    const int wm = (warp & 3) * 32;    // 4 warps along M
    const int wn = (warp >> 2) * 64;   // 2 warps along N

    const int bm = blockIdx.y * BM;
    const int bn = blockIdx.x * BN;

    // ldmatrix per-lane address components (half-element offsets)
    const int ar = lane & 15;                         // A row within 16
    const int ak = (lane >> 4) * 8;                   // A k-offset (0/8)
    const int br = ((lane >> 4) << 3) + (lane & 7);   // B row within 16
    const int bk = ((lane >> 3) & 1) * 8;             // B k-offset (0/8)

    // Tile-load indexing: 16B chunk = 8 halves; 8 chunks per row (BK=64).
    const int chunk = (tid & 7) * 8;      // half offset in row
    const int rowb  = tid >> 3;           // 0..31

    float acc[2][8][4];
    #pragma unroll
    for (int mt = 0; mt < 2; mt++)
        #pragma unroll
        for (int nt = 0; nt < 8; nt++)
            #pragma unroll
            for (int r = 0; r < 4; r++)
                acc[mt][nt][r] = 0.f;

    auto load_tiles = [&](int s, int k0) {
        uint32_t As = smem_b + s * STAGE_BYTES;
        uint32_t Bs = As + A_BYTES;
        // A: 128 rows -> 4 passes of 32 rows
        #pragma unroll
        for (int i = 0; i < 4; i++) {
            int row  = rowb + i * 32;
            int arow = bm + row;
            const __half* ga = g_aggh + (size_t)arow * D + k0 + chunk;
            uint32_t da = As + (row * LDT + chunk) * 2;
            int sz = (arow < N_SRC) ? 16 : 0;   // zero-fill OOB rows
            asm volatile("cp.async.cg.shared.global [%0], [%1], 16, %2;"
                         :: "r"(da), "l"(ga), "r"(sz));
        }
        // B: 128 rows (always in-bounds: bn+row < 512)
        #pragma unroll
        for (int i = 0; i < 4; i++) {
            int row = rowb + i * 32;
            const __half* gb = g_Wh + (size_t)(bn + row) * D + k0 + chunk;
            uint32_t db = Bs + (row * LDT + chunk) * 2;
            asm volatile("cp.async.cg.shared.global [%0], [%1], 16;"
                         :: "r"(db), "l"(gb));
        }
        asm volatile("cp.async.commit_group;");
    };

    const int NK = D / BK;   // 8
    load_tiles(0, 0);

    for (int ks = 0; ks < NK; ks++) {
        asm volatile("cp.async.wait_group 0;" ::: "memory");
        __syncthreads();
        if (ks + 1 < NK) load_tiles((ks + 1) & 1, (ks + 1) * BK);

        uint32_t As = smem_b + (ks & 1) * STAGE_BYTES;
        uint32_t Bs = As + A_BYTES;

        // per-lane ldmatrix base addresses (bytes)
        uint32_t aaddr[2], baddr[4];
        #pragma unroll
        for (int mt = 0; mt < 2; mt++)
            aaddr[mt] = As + ((wm + mt * 16 + ar) * LDT + ak) * 2;
        #pragma unroll
        for (int np = 0; np < 4; np++)
            baddr[np] = Bs + ((wn + np * 16 + br) * LDT + bk) * 2;

        #pragma unroll
        for (int kk = 0; kk < BK; kk += 16) {   // 4 x K16 steps
            unsigned afr[2][4];
            unsigned bfr[8][2];
            #pragma unroll
            for (int mt = 0; mt < 2; mt++)
                ldsm_x4(afr[mt], aaddr[mt] + kk * 2);
            #pragma unroll
            for (int np = 0; np < 4; np++) {
                unsigned r[4];
                ldsm_x4(r, baddr[np] + kk * 2);
                bfr[np * 2    ][0] = r[0];
                bfr[np * 2    ][1] = r[1];
                bfr[np * 2 + 1][0] = r[2];
                bfr[np * 2 + 1][1] = r[3];
            }
            #pragma unroll
            for (int mt = 0; mt < 2; mt++)
                #pragma unroll
                for (int nt = 0; nt < 8; nt++)
                    mma_f16_16x8x16(acc[mt][nt], afr[mt], bfr[nt], acc[mt][nt]);
        }
        __syncthreads();
    }

    // Epilogue: add bias, store
    #pragma unroll
    for (int mt = 0; mt < 2; mt++) {
        int row0 = bm + wm + mt * 16 + g;
        int row1 = row0 + 8;
        #pragma unroll
        for (int nt = 0; nt < 8; nt++) {
            int col = bn + wn + nt * 8 + 2 * t;
            float b0 = __ldg(bias + col);
            float b1 = __ldg(bias + col + 1);
            if (row0 < N_SRC) {
                out[(size_t)row0 * D + col    ] = acc[mt][nt][0] + b0;
                out[(size_t)row0 * D + col + 1] = acc[mt][nt][1] + b1;
            }
            if (row1 < N_SRC) {
                out[(size_t)row1 * D + col    ] = acc[mt][nt][2] + b0;
                out[(size_t)row1 * D + col + 1] = acc[mt][nt][3] + b1;
            }
        }
    }
}

// ---------------------------------------------------------------------------
// Launch. Inputs per metadata order:
//   0: src_h [50000,512] f32   1: W [512,512] f32   2: b [512] f32
//   3: src_idx [150000] i32    4: dst_idx [150000] i32   5: n_dst scalar
// ---------------------------------------------------------------------------
extern "C" void kernel_launch(void* const* d_in, const int* in_sizes, int n_in,
                              void* d_out, int out_size)
{
    const float* src_h   = (const float*)d_in[0];
    const float* W       = (const float*)d_in[1];
    const float* bias    = (const float*)d_in[2];
    const int*   src_idx = (const int*)d_in[3];
    const int*   dst_idx = (const int*)d_in[4];
    float*       out     = (float*)d_out;

    cudaFuncSetAttribute(gemm_kernel,
                         cudaFuncAttributeMaxDynamicSharedMemorySize,
                         GEMM_SMEM_BYTES);

    prep_kernel<<<PREP_BLOCKS, 256>>>(W, src_h);
    hist_kernel<<<NBLK_E, 256>>>(dst_idx);
    scan1_kernel<<<NBLK_N, 256>>>();
    scan3_kernel<<<NBLK_N, 256>>>();
    fill_kernel<<<NBLK_E, 256>>>(src_idx, dst_idx);
    aggregate_kernel<<<N_SRC, 128>>>();

    dim3 grid(D / BN, (N_SRC + BM - 1) / BM);   // (4, 391)
    gemm_kernel<<<grid, 256, GEMM_SMEM_BYTES>>>(bias, out);
}

// round 10
// speedup vs baseline: 3.0727x; 1.0641x over previous
#include <cuda_runtime.h>
#include <cuda_fp16.h>
#include <cstdint>

// Problem constants (fixed by the dataset)
#define N_SRC   50000
#define N_EDGES 150000
#define D       512
#define NBLK_N  196          // ceil(N_SRC / 256)
#define NBLK_E  587          // ceil(N_EDGES / 256)

// ---------------------------------------------------------------------------
// Device scratch (no allocations allowed)
// ---------------------------------------------------------------------------
__device__ __half g_aggh[(size_t)N_SRC * D];   // aggregated messages (fp16)
__device__ __half g_Wh[(size_t)D * D];         // W rounded to fp16
__device__ int    g_count[N_SRC];
__device__ int    g_offset[N_SRC + 1];
__device__ int    g_cursor[N_SRC];
__device__ int    g_bsum[256];
__device__ int    g_sorted_src[N_EDGES];

__device__ __forceinline__ void mma_f16_16x8x16(
    float d[4], const unsigned a[4], const unsigned b[2], const float c[4])
{
    asm volatile(
        "mma.sync.aligned.m16n8k16.row.col.f32.f16.f16.f32 "
        "{%0,%1,%2,%3}, {%4,%5,%6,%7}, {%8,%9}, {%10,%11,%12,%13};"
        : "=f"(d[0]), "=f"(d[1]), "=f"(d[2]), "=f"(d[3])
        : "r"(a[0]), "r"(a[1]), "r"(a[2]), "r"(a[3]),
          "r"(b[0]), "r"(b[1]),
          "f"(c[0]), "f"(c[1]), "f"(c[2]), "f"(c[3]));
}

__device__ __forceinline__ void ldsm_x4(unsigned r[4], unsigned addr) {
    asm volatile("ldmatrix.sync.aligned.m8n8.x4.shared.b16 {%0,%1,%2,%3}, [%4];"
                 : "=r"(r[0]), "=r"(r[1]), "=r"(r[2]), "=r"(r[3]) : "r"(addr));
}

// ---------------------------------------------------------------------------
// CSR construction
// ---------------------------------------------------------------------------
__global__ void zero_count_kernel() {
    int i = blockIdx.x * 256 + threadIdx.x;
    if (i < N_SRC) g_count[i] = 0;
    if (i == 0)    g_offset[N_SRC] = N_EDGES;
}

// Histogram + (independent) W->fp16 conversion folded together
__global__ void hist_kernel(const int* __restrict__ dst_idx,
                            const float* __restrict__ W) {
    int e = blockIdx.x * 256 + threadIdx.x;
    if (e < N_EDGES) atomicAdd(&g_count[dst_idx[e]], 1);
    // W: 65536 float4s over 150272 threads
    if (e < (D * D) / 4) {
        float4 v = reinterpret_cast<const float4*>(W)[e];
        __half2 h0 = __floats2half2_rn(v.x, v.y);
        __half2 h1 = __floats2half2_rn(v.z, v.w);
        uint2 u;
        u.x = *reinterpret_cast<unsigned*>(&h0);
        u.y = *reinterpret_cast<unsigned*>(&h1);
        reinterpret_cast<uint2*>(g_Wh)[e] = u;
    }
}

__global__ void scan1_kernel() {
    __shared__ int sh[256];
    int t = threadIdx.x;
    int idx = blockIdx.x * 256 + t;
    int v = (idx < N_SRC) ? g_count[idx] : 0;
    sh[t] = v; __syncthreads();
    #pragma unroll
    for (int off = 1; off < 256; off <<= 1) {
        int x = (t >= off) ? sh[t - off] : 0;
        __syncthreads();
        sh[t] += x;
        __syncthreads();
    }
    if (idx < N_SRC) g_offset[idx] = sh[t] - v;
    if (t == 255)    g_bsum[blockIdx.x] = sh[255];
}

// scan3 with integrated block-sum prefix
__global__ void scan3_kernel() {
    __shared__ int s_base;
    int t = threadIdx.x;
    if (t == 0) s_base = 0;
    __syncthreads();
    int partial = 0;
    for (int j = t; j < blockIdx.x; j += 256) partial += g_bsum[j];
    if (partial) atomicAdd(&s_base, partial);
    __syncthreads();
    int i = blockIdx.x * 256 + t;
    if (i < N_SRC) {
        int o = g_offset[i] + s_base;
        g_offset[i] = o;
        g_cursor[i] = o;
    }
}

__global__ void fill_kernel(const int* __restrict__ src_idx,
                            const int* __restrict__ dst_idx) {
    int e = blockIdx.x * 256 + threadIdx.x;
    if (e < N_EDGES) {
        int pos = atomicAdd(&g_cursor[dst_idx[e]], 1);
        g_sorted_src[pos] = src_idx[e];
    }
}

// ---------------------------------------------------------------------------
// Gather-aggregate: one block (128 threads) per dst node. Gathers f32 rows
// directly (src rows stay L2-hot across the ~3x reuse), accumulates in fp32,
// writes fp16 rows once.
// ---------------------------------------------------------------------------
__global__ void __launch_bounds__(128) aggregate_kernel(
    const float* __restrict__ src_h)
{
    int d = blockIdx.x;
    int t = threadIdx.x;                 // 0..127 -> one float4 each
    int start = g_offset[d];
    int end   = g_offset[d + 1];
    float4 acc = make_float4(0.f, 0.f, 0.f, 0.f);
    for (int j = start; j < end; j++) {
        int s = g_sorted_src[j];
        float4 v = reinterpret_cast<const float4*>(src_h + (size_t)s * D)[t];
        acc.x += v.x; acc.y += v.y; acc.z += v.z; acc.w += v.w;
    }
    __half2 h0 = __floats2half2_rn(acc.x, acc.y);
    __half2 h1 = __floats2half2_rn(acc.z, acc.w);
    uint2 u;
    u.x = *reinterpret_cast<unsigned*>(&h0);
    u.y = *reinterpret_cast<unsigned*>(&h1);
    reinterpret_cast<uint2*>(g_aggh + (size_t)d * D)[t] = u;
}

// ---------------------------------------------------------------------------
// GEMM: out = agg @ W^T + b, FP16 mma.m16n8k16 (f32 accum).
// BM=128, BN=128, BK=64 halves; 256 threads, 8 warps (4M x 2N), warp 32x64.
// 2 CTAs/SM, 3-stage cp.async pipeline (wait_group 1), ldmatrix fragments.
// smem row stride 72 halves (144B): 16B-aligned, ldmatrix conflict-free.
// ---------------------------------------------------------------------------
#define BM 128
#define BN 128
#define BK 64
#define LDT 72
#define A_BYTES (BM * LDT * 2)              // 18432
#define STAGE_BYTES (2 * A_BYTES)           // A + B = 36864
#define NSTAGE 3
#define GEMM_SMEM_BYTES (NSTAGE * STAGE_BYTES)   // 110592

__global__ void __launch_bounds__(256, 2) gemm_kernel(
    const float* __restrict__ bias,
    float*       __restrict__ out)
{
    extern __shared__ __half smem[];
    uint32_t smem_b;
    {
        uint64_t tmp = __cvta_generic_to_shared(smem);
        smem_b = (uint32_t)tmp;
    }

    const int tid  = threadIdx.x;
    const int warp = tid >> 5;
    const int lane = tid & 31;
    const int g    = lane >> 2;   // 0..7
    const int t    = lane & 3;    // 0..3

    const int wm = (warp & 3) * 32;    // 4 warps along M
    const int wn = (warp >> 2) * 64;   // 2 warps along N

    const int bm = blockIdx.y * BM;
    const int bn = blockIdx.x * BN;

    // ldmatrix per-lane address components (half-element offsets)
    const int ar = lane & 15;                         // A row within 16
    const int ak = (lane >> 4) * 8;                   // A k-offset (0/8)
    const int br = ((lane >> 4) << 3) + (lane & 7);   // B row within 16
    const int bk = ((lane >> 3) & 1) * 8;             // B k-offset (0/8)

    // Tile-load indexing: 16B chunk = 8 halves; 8 chunks per row (BK=64).
    const int chunk = (tid & 7) * 8;      // half offset in row
    const int rowb  = tid >> 3;           // 0..31

    float acc[2][8][4];
    #pragma unroll
    for (int mt = 0; mt < 2; mt++)
        #pragma unroll
        for (int nt = 0; nt < 8; nt++)
            #pragma unroll
            for (int r = 0; r < 4; r++)
                acc[mt][nt][r] = 0.f;

    auto load_tiles = [&](int s, int k0) {
        uint32_t As = smem_b + s * STAGE_BYTES;
        uint32_t Bs = As + A_BYTES;
        // A: 128 rows -> 4 passes of 32 rows
        #pragma unroll
        for (int i = 0; i < 4; i++) {
            int row  = rowb + i * 32;
            int arow = bm + row;
            const __half* ga = g_aggh + (size_t)arow * D + k0 + chunk;
            uint32_t da = As + (row * LDT + chunk) * 2;
            int sz = (arow < N_SRC) ? 16 : 0;   // zero-fill OOB rows
            asm volatile("cp.async.cg.shared.global [%0], [%1], 16, %2;"
                         :: "r"(da), "l"(ga), "r"(sz));
        }
        // B: 128 rows (always in-bounds: bn+row < 512)
        #pragma unroll
        for (int i = 0; i < 4; i++) {
            int row = rowb + i * 32;
            const __half* gb = g_Wh + (size_t)(bn + row) * D + k0 + chunk;
            uint32_t db = Bs + (row * LDT + chunk) * 2;
            asm volatile("cp.async.cg.shared.global [%0], [%1], 16;"
                         :: "r"(db), "l"(gb));
        }
        asm volatile("cp.async.commit_group;");
    };

    const int NK = D / BK;   // 8
    load_tiles(0, 0);
    load_tiles(1, BK);

    int buf = 0;
    for (int ks = 0; ks < NK; ks++) {
        asm volatile("cp.async.wait_group 1;" ::: "memory");
        __syncthreads();
        if (ks + 2 < NK) {
            int nb = buf + 2; if (nb >= NSTAGE) nb -= NSTAGE;
            load_tiles(nb, (ks + 2) * BK);
        }

        uint32_t As = smem_b + buf * STAGE_BYTES;
        uint32_t Bs = As + A_BYTES;

        // per-lane ldmatrix base addresses (bytes)
        uint32_t aaddr[2], baddr[4];
        #pragma unroll
        for (int mt = 0; mt < 2; mt++)
            aaddr[mt] = As + ((wm + mt * 16 + ar) * LDT + ak) * 2;
        #pragma unroll
        for (int np = 0; np < 4; np++)
            baddr[np] = Bs + ((wn + np * 16 + br) * LDT + bk) * 2;

        #pragma unroll
        for (int kk = 0; kk < BK; kk += 16) {   // 4 x K16 steps
            unsigned afr[2][4];
            unsigned bfr[8][2];
            #pragma unroll
            for (int mt = 0; mt < 2; mt++)
                ldsm_x4(afr[mt], aaddr[mt] + kk * 2);
            #pragma unroll
            for (int np = 0; np < 4; np++) {
                unsigned r[4];
                ldsm_x4(r, baddr[np] + kk * 2);
                bfr[np * 2    ][0] = r[0];
                bfr[np * 2    ][1] = r[1];
                bfr[np * 2 + 1][0] = r[2];
                bfr[np * 2 + 1][1] = r[3];
            }
            #pragma unroll
            for (int mt = 0; mt < 2; mt++)
                #pragma unroll
                for (int nt = 0; nt < 8; nt++)
                    mma_f16_16x8x16(acc[mt][nt], afr[mt], bfr[nt], acc[mt][nt]);
        }
        if (++buf >= NSTAGE) buf = 0;
    }

    // Epilogue: add bias, store
    #pragma unroll
    for (int mt = 0; mt < 2; mt++) {
        int row0 = bm + wm + mt * 16 + g;
        int row1 = row0 + 8;
        #pragma unroll
        for (int nt = 0; nt < 8; nt++) {
            int col = bn + wn + nt * 8 + 2 * t;
            float b0 = __ldg(bias + col);
            float b1 = __ldg(bias + col + 1);
            if (row0 < N_SRC) {
                out[(size_t)row0 * D + col    ] = acc[mt][nt][0] + b0;
                out[(size_t)row0 * D + col + 1] = acc[mt][nt][1] + b1;
            }
            if (row1 < N_SRC) {
                out[(size_t)row1 * D + col    ] = acc[mt][nt][2] + b0;
                out[(size_t)row1 * D + col + 1] = acc[mt][nt][3] + b1;
            }
        }
    }
}

// ---------------------------------------------------------------------------
// Launch. Inputs per metadata order:
//   0: src_h [50000,512] f32   1: W [512,512] f32   2: b [512] f32
//   3: src_idx [150000] i32    4: dst_idx [150000] i32   5: n_dst scalar
// ---------------------------------------------------------------------------
extern "C" void kernel_launch(void* const* d_in, const int* in_sizes, int n_in,
                              void* d_out, int out_size)
{
    const float* src_h   = (const float*)d_in[0];
    const float* W       = (const float*)d_in[1];
    const float* bias    = (const float*)d_in[2];
    const int*   src_idx = (const int*)d_in[3];
    const int*   dst_idx = (const int*)d_in[4];
    float*       out     = (float*)d_out;

    cudaFuncSetAttribute(gemm_kernel,
                         cudaFuncAttributeMaxDynamicSharedMemorySize,
                         GEMM_SMEM_BYTES);

    zero_count_kernel<<<NBLK_N, 256>>>();
    hist_kernel<<<NBLK_E, 256>>>(dst_idx, W);
    scan1_kernel<<<NBLK_N, 256>>>();
    scan3_kernel<<<NBLK_N, 256>>>();
    fill_kernel<<<NBLK_E, 256>>>(src_idx, dst_idx);
    aggregate_kernel<<<N_SRC, 128>>>(src_h);

    dim3 grid(D / BN, (N_SRC + BM - 1) / BM);   // (4, 391)
    gemm_kernel<<<grid, 256, GEMM_SMEM_BYTES>>>(bias, out);
}